// round 7
// baseline (speedup 1.0000x reference)
#include <cuda_runtime.h>
#include <cstdint>

// ---------------- problem constants ----------------
constexpr int NN  = 38000;   // nodes
constexpr int IND = 64;      // input dim
constexpr int HID = 128;
constexpr int RR  = 8;       // relations
constexpr int EE  = 200000;  // edges per relation
constexpr int NR  = 60000;   // rows
constexpr int FF  = 19;      // features per row
constexpr int NC  = 10;      // classes

// ---------------- device scratch (static, no allocation) ----------------
__device__ float g_h0[(size_t)NN * HID];     // relu(X @ W_in + b_in)
__device__ float g_acc1[(size_t)NN * HID];   // layer-1 accumulator (pre-relu)
__device__ float g_acc2[(size_t)NN * HID];   // layer-2 accumulator (= h2)
__device__ float g_z[(size_t)NN * HID];      // per-relation transformed feats
__device__ float g_deg_out[RR * NN];
__device__ float g_deg_in[RR * NN];
__device__ float g_norm_s[RR * NN];
__device__ float g_norm_d[RR * NN];
__device__ float g_mean[(size_t)NR * HID];
__device__ float g_x1[(size_t)NR * HID];
__device__ float g_x2[(size_t)NR * HID];
__device__ int   g_mask_is_int;

// ---------------- zero ----------------
__global__ void k_zero4(float4* p, long long n4) {
    long long i = (long long)blockIdx.x * blockDim.x + threadIdx.x;
    long long stride = (long long)gridDim.x * blockDim.x;
    float4 z = make_float4(0.f, 0.f, 0.f, 0.f);
    for (; i < n4; i += stride) p[i] = z;
}

// ---------------- mask dtype detection (bool stored as u8 vs i32) ----------
__global__ void k_detect_mask(const unsigned char* __restrict__ m) {
    __shared__ int cnt;
    if (threadIdx.x == 0) cnt = 0;
    __syncthreads();
    int local = 0;
    for (int i = threadIdx.x; i < 65536; i += blockDim.x)
        local += (m[i] != 0);
    atomicAdd(&cnt, local);
    __syncthreads();
    if (threadIdx.x == 0) g_mask_is_int = (cnt < 16384) ? 1 : 0;
}

// ---------------- degrees + norms ----------------
__global__ void k_deg(const int* __restrict__ src, const int* __restrict__ dst) {
    long long i = (long long)blockIdx.x * blockDim.x + threadIdx.x;
    if (i >= (long long)RR * EE) return;
    int r = (int)(i / EE);
    atomicAdd(&g_deg_out[r * NN + src[i]], 1.f);
    atomicAdd(&g_deg_in [r * NN + dst[i]], 1.f);
}

__global__ void k_norms() {
    int i = blockIdx.x * blockDim.x + threadIdx.x;
    if (i >= RR * NN) return;
    g_norm_s[i] = rsqrtf(fmaxf(g_deg_out[i], 1.f));
    g_norm_d[i] = rsqrtf(fmaxf(g_deg_in [i], 1.f));
}

// ---------------- accumulator init: acc[n][c] = sum_r b[r][c] ----------------
__global__ void k_bias_init(const float* __restrict__ b, float* __restrict__ acc) {
    long long i = (long long)blockIdx.x * blockDim.x + threadIdx.x;
    if (i >= (long long)NN * HID) return;
    int c = (int)(i & (HID - 1));
    float s = 0.f;
#pragma unroll
    for (int r = 0; r < RR; r++) s += __ldg(&b[r * HID + c]);
    acc[i] = s;
}

// ---------------- per-relation edge scatter: acc[dst] += z[src] * norm_d[dst] ---
__global__ void k_agg2(const float* __restrict__ z,
                       const int* __restrict__ src, const int* __restrict__ dst,
                       const float* __restrict__ norm_d_r, float* __restrict__ acc) {
    long long gtid = (long long)blockIdx.x * blockDim.x + threadIdx.x;
    long long w = gtid >> 5;
    if (w >= EE) return;
    int lane = threadIdx.x & 31;
    int s = __ldg(&src[w]);
    int d = __ldg(&dst[w]);
    float nd = __ldg(&norm_d_r[d]);
    float4 v = __ldg((const float4*)(z + (size_t)s * HID) + lane);
    v.x *= nd; v.y *= nd; v.z *= nd; v.w *= nd;
    atomicAdd((float4*)(acc + (size_t)d * HID) + lane, v);
}

// ---------------- FMA-bound tiled GEMM: C[M][128] = epi(pre(A)[M][K] @ B[K][128]) ---
// BM=128, BN=128, BK=16, 256 threads, 8x8 per-thread micro-tile.
// pre(A): optional relu, optional per-row scale. epi: optional bias + relu.
template <bool RELU_EPI, bool RELU_IN, bool SCALE_A, bool BIAS>
__global__ __launch_bounds__(256, 2)
void k_gemm128(const float* __restrict__ A, const float* __restrict__ B,
               const float* __restrict__ bias, const float* __restrict__ ascale,
               float* __restrict__ C, int M, int K) {
    __shared__ float As[16][132];   // [k][m], padded
    __shared__ float Bs[16][128];
    const int tid = threadIdx.x;
    const int row_t = tid >> 4;    // 0..15 -> 8 rows each
    const int col_t = tid & 15;    // 0..15 -> 8 cols each
    const int m0 = blockIdx.x * 128;

    float acc[8][8];
#pragma unroll
    for (int i = 0; i < 8; i++)
#pragma unroll
        for (int j = 0; j < 8; j++) acc[i][j] = 0.f;

    const int a_m = tid >> 1;          // 0..127
    const int a_h = (tid & 1) * 4;     // k-quad base 0 or 4; second pass +8
    const int b_k = tid >> 5;          // 0..7
    const int b_j = (tid & 31) * 4;

    const int arow = m0 + a_m;
    float s = 1.f;
    if (SCALE_A) s = (arow < M) ? __ldg(&ascale[arow]) : 0.f;

    for (int k0 = 0; k0 < K; k0 += 16) {
#pragma unroll
        for (int t = 0; t < 2; t++) {
            int kq = a_h + t * 8;
            float4 av = make_float4(0.f, 0.f, 0.f, 0.f);
            if (arow < M)
                av = *(const float4*)(A + (size_t)arow * K + k0 + kq);
            if (RELU_IN) {
                av.x = fmaxf(av.x, 0.f); av.y = fmaxf(av.y, 0.f);
                av.z = fmaxf(av.z, 0.f); av.w = fmaxf(av.w, 0.f);
            }
            if (SCALE_A) { av.x *= s; av.y *= s; av.z *= s; av.w *= s; }
            As[kq + 0][a_m] = av.x;
            As[kq + 1][a_m] = av.y;
            As[kq + 2][a_m] = av.z;
            As[kq + 3][a_m] = av.w;
        }
        *(float4*)&Bs[b_k    ][b_j] = *(const float4*)(B + (size_t)(k0 + b_k    ) * HID + b_j);
        *(float4*)&Bs[b_k + 8][b_j] = *(const float4*)(B + (size_t)(k0 + b_k + 8) * HID + b_j);
        __syncthreads();
#pragma unroll
        for (int k = 0; k < 16; k++) {
            float4 a0 = *(float4*)&As[k][row_t * 8];
            float4 a1 = *(float4*)&As[k][row_t * 8 + 4];
            float4 b0 = *(float4*)&Bs[k][col_t * 8];
            float4 b1 = *(float4*)&Bs[k][col_t * 8 + 4];
            float ar[8] = {a0.x, a0.y, a0.z, a0.w, a1.x, a1.y, a1.z, a1.w};
            float br[8] = {b0.x, b0.y, b0.z, b0.w, b1.x, b1.y, b1.z, b1.w};
#pragma unroll
            for (int i = 0; i < 8; i++)
#pragma unroll
                for (int j = 0; j < 8; j++) acc[i][j] += ar[i] * br[j];
        }
        __syncthreads();
    }

    float bj[8];
#pragma unroll
    for (int j = 0; j < 8; j++) bj[j] = BIAS ? __ldg(&bias[col_t * 8 + j]) : 0.f;
#pragma unroll
    for (int i = 0; i < 8; i++) {
        int row = m0 + row_t * 8 + i;
        if (row < M) {
            float o[8];
#pragma unroll
            for (int j = 0; j < 8; j++) {
                o[j] = acc[i][j] + bj[j];
                if (RELU_EPI) o[j] = fmaxf(o[j], 0.f);
            }
            *(float4*)(C + (size_t)row * HID + col_t * 8)     = make_float4(o[0], o[1], o[2], o[3]);
            *(float4*)(C + (size_t)row * HID + col_t * 8 + 4) = make_float4(o[4], o[5], o[6], o[7]);
        }
    }
}

// ---------------- ragged masked mean: one warp per row ----------------
__global__ void k_rowmean(const float* __restrict__ h, const int* __restrict__ ridx,
                          const unsigned char* __restrict__ rmask, float* __restrict__ outm) {
    long long gtid = (long long)blockIdx.x * blockDim.x + threadIdx.x;
    long long w = gtid >> 5;
    if (w >= NR) return;
    int lane = threadIdx.x & 31;
    const int is_int = g_mask_is_int;
    const int* rmask_i = (const int*)rmask;
    float4 acc = make_float4(0.f, 0.f, 0.f, 0.f);
    float cnt = 0.f;
#pragma unroll
    for (int f = 0; f < FF; f++) {
        bool on = is_int ? (__ldg(&rmask_i[w * FF + f]) != 0)
                         : (rmask[w * FF + f] != 0);
        if (on) {
            int idx = __ldg(&ridx[w * FF + f]);
            float4 v = __ldg((const float4*)(h + (size_t)idx * HID) + lane);
            acc.x += v.x; acc.y += v.y; acc.z += v.z; acc.w += v.w;
            cnt += 1.f;
        }
    }
    float inv = 1.f / fmaxf(cnt, 1.f);
    acc.x *= inv; acc.y *= inv; acc.z *= inv; acc.w *= inv;
    *((float4*)(outm + (size_t)w * HID) + lane) = acc;
}

// ---------------- final head: [NR][128] @ [128][10] + b ----------------
__global__ void k_head(const float* __restrict__ X, const float* __restrict__ W,
                       const float* __restrict__ b, float* __restrict__ out) {
    long long t = (long long)blockIdx.x * blockDim.x + threadIdx.x;
    int row = (int)(t >> 4);
    int c = (int)(t & 15);
    if (row >= NR || c >= NC) return;
    const float* x = X + (size_t)row * HID;
    float acc = b[c];
#pragma unroll
    for (int k = 0; k < HID; k++) acc += x[k] * __ldg(&W[k * NC + c]);
    out[(size_t)row * NC + c] = acc;
}

// ---------------- launch ----------------
extern "C" void kernel_launch(void* const* d_in, const int* in_sizes, int n_in,
                              void* d_out, int out_size) {
    const float* node_feats = (const float*)d_in[0];
    const int*   edges_src  = (const int*)  d_in[1];
    const int*   edges_dst  = (const int*)  d_in[2];
    const int*   row_idx    = (const int*)  d_in[3];
    const unsigned char* row_mask = (const unsigned char*)d_in[4];
    const float* W_in = (const float*)d_in[5];
    const float* b_in = (const float*)d_in[6];
    const float* W1   = (const float*)d_in[7];
    const float* b1   = (const float*)d_in[8];
    const float* W2   = (const float*)d_in[9];
    const float* b2   = (const float*)d_in[10];
    const float* Wm1  = (const float*)d_in[11];
    const float* bm1  = (const float*)d_in[12];
    const float* Wm2  = (const float*)d_in[13];
    const float* bm2  = (const float*)d_in[14];
    const float* Wm3  = (const float*)d_in[15];
    const float* bm3  = (const float*)d_in[16];
    float* out = (float*)d_out;

    float *p_h0, *p_acc1, *p_acc2, *p_z, *p_dego, *p_degi, *p_ns, *p_nd,
          *p_mean, *p_x1, *p_x2;
    cudaGetSymbolAddress((void**)&p_h0,   g_h0);
    cudaGetSymbolAddress((void**)&p_acc1, g_acc1);
    cudaGetSymbolAddress((void**)&p_acc2, g_acc2);
    cudaGetSymbolAddress((void**)&p_z,    g_z);
    cudaGetSymbolAddress((void**)&p_dego, g_deg_out);
    cudaGetSymbolAddress((void**)&p_degi, g_deg_in);
    cudaGetSymbolAddress((void**)&p_ns,   g_norm_s);
    cudaGetSymbolAddress((void**)&p_nd,   g_norm_d);
    cudaGetSymbolAddress((void**)&p_mean, g_mean);
    cudaGetSymbolAddress((void**)&p_x1,   g_x1);
    cudaGetSymbolAddress((void**)&p_x2,   g_x2);

    const long long deg4 = (long long)RR * NN / 4;
    const int gemm_blocks_nn = (NN + 127) / 128;
    const int gemm_blocks_nr = (NR + 127) / 128;
    const unsigned agg_blocks = (unsigned)(((long long)EE * 32 + 255) / 256);
    const int bias_blocks = (int)(((long long)NN * HID + 255) / 256);

    // mask dtype detection
    k_detect_mask<<<1, 256>>>(row_mask);

    // degrees + norms
    k_zero4<<<2048, 256>>>((float4*)p_dego, deg4);
    k_zero4<<<2048, 256>>>((float4*)p_degi, deg4);
    k_deg<<<(RR * EE + 255) / 256, 256>>>(edges_src, edges_dst);
    k_norms<<<(RR * NN + 255) / 256, 256>>>();

    // input linear + relu: h0 = relu(X @ W_in + b_in)
    k_gemm128<true, false, false, true><<<gemm_blocks_nn, 256>>>(
        node_feats, W_in, b_in, nullptr, p_h0, NN, IND);

    // ---- RGCN layer 1: acc1 = sum_r scatter( (norm_s_r . h0) @ W1_r ) * norm_d_r + sum_r b1_r
    k_bias_init<<<bias_blocks, 256>>>(b1, p_acc1);
    for (int r = 0; r < RR; r++) {
        k_gemm128<false, false, true, false><<<gemm_blocks_nn, 256>>>(
            p_h0, W1 + (size_t)r * HID * HID, nullptr, p_ns + (size_t)r * NN,
            p_z, NN, HID);
        k_agg2<<<agg_blocks, 256>>>(p_z, edges_src + (size_t)r * EE,
                                    edges_dst + (size_t)r * EE,
                                    p_nd + (size_t)r * NN, p_acc1);
    }

    // ---- RGCN layer 2: relu folded into A-load of the relation GEMMs
    k_bias_init<<<bias_blocks, 256>>>(b2, p_acc2);
    for (int r = 0; r < RR; r++) {
        k_gemm128<false, true, true, false><<<gemm_blocks_nn, 256>>>(
            p_acc1, W2 + (size_t)r * HID * HID, nullptr, p_ns + (size_t)r * NN,
            p_z, NN, HID);
        k_agg2<<<agg_blocks, 256>>>(p_z, edges_src + (size_t)r * EE,
                                    edges_dst + (size_t)r * EE,
                                    p_nd + (size_t)r * NN, p_acc2);
    }

    // ragged masked mean over acc2 (= h2, no relu)
    {
        long long nt = (long long)NR * 32;
        k_rowmean<<<(unsigned)((nt + 255) / 256), 256>>>(p_acc2, row_idx, row_mask, p_mean);
    }

    // MLP head
    k_gemm128<true, false, false, true><<<gemm_blocks_nr, 256>>>(
        p_mean, Wm1, bm1, nullptr, p_x1, NR, HID);
    k_gemm128<true, false, false, true><<<gemm_blocks_nr, 256>>>(
        p_x1, Wm2, bm2, nullptr, p_x2, NR, HID);
    k_head<<<(NR * 16 + 255) / 256, 256>>>(p_x2, Wm3, bm3, out);

    (void)in_sizes; (void)n_in; (void)out_size;
}